// round 13
// baseline (speedup 1.0000x reference)
#include <cuda_runtime.h>
#include <math.h>
#include <stdint.h>

#define S_LEN  2048
#define HIDDEN 2048
#define NHEADS 16
#define NKV    4
#define HD     128
#define BATCH  2
#define NQ     (NHEADS*HD)          // 2048
#define NKVD   (NKV*HD)             // 512
#define NTOT   (NQ + 2*NKVD)        // 3072
#define MROWS  (BATCH*S_LEN)        // 4096
#define BHQ    (BATCH*NHEADS)       // 32
#define MASK_N 4194304

// Scratch (device globals: no allocation allowed)
__device__ float g_qkv[(size_t)MROWS*NTOT];             // [m, 3072] flat QKV proj
__device__ float g_q[(size_t)BATCH*NHEADS*S_LEN*HD];    // [b,h,s,d]
__device__ float g_k[(size_t)BATCH*NKV*S_LEN*HD];       // [b,h,s,d]
__device__ float g_v[(size_t)BATCH*NKV*S_LEN*HD];       // [b,h,s,d]
__device__ float g_attn[(size_t)BATCH*S_LEN*NHEADS*HD]; // [b,s,h*d]
__device__ float g_s[(size_t)BHQ*S_LEN*S_LEN];          // [bh,q,k] scores/probs

// Runtime-resolved pointers (set by resolve_kernel on device)
__device__ const float* g_qw_ptr;
__device__ const float* g_ow_ptr;
__device__ const float* g_mask_ptr;

// ---------------------------------------------------------------------------
// Resolve {attention_mask, q_w, o_w} among the three 4194304-elem buffers.
// Mask = buffer with most-negative global min. q_w vs o_w by convention flag.
// ---------------------------------------------------------------------------
__global__ void resolve_kernel(const float* c0, const float* c1, const float* c2,
                               int wFirst)
{
    __shared__ float smin[3][256];
    const float* c[3] = {c0, c1, c2};
    const int tid = threadIdx.x;

    for (int i = 0; i < 3; i++) {
        float mn = 3.4e38f;
        for (int e = tid; e < MASK_N; e += 256)
            mn = fminf(mn, c[i][e]);
        smin[i][tid] = mn;
    }
    __syncthreads();
    if (tid == 0) {
        float mn[3];
        for (int i = 0; i < 3; i++) {
            float m = 3.4e38f;
            for (int t = 0; t < 256; t++) m = fminf(m, smin[i][t]);
            mn[i] = m;
        }
        int mi = 0;
        if (mn[1] < mn[mi]) mi = 1;
        if (mn[2] < mn[mi]) mi = 2;
        g_mask_ptr = c[mi];
        const float* nm[2];
        int j = 0;
        for (int i = 0; i < 3; i++)
            if (i != mi) nm[j++] = c[i];
        if (wFirst) { g_qw_ptr = nm[0]; g_ow_ptr = nm[1]; }
        else        { g_qw_ptr = nm[1]; g_ow_ptr = nm[0]; }
    }
}

// ---------------------------------------------------------------------------
// Textbook GEMM: C[m][n] = sum_k A[m][k] * W[n][k] (+ bias[n] if given).
// wsel: 0 -> use W param, 1 -> g_qw_ptr, 2 -> g_ow_ptr.
// ---------------------------------------------------------------------------
__global__ void gemm64(const float* __restrict__ A,
                       const float* __restrict__ Wparam,
                       const float* __restrict__ bias,
                       float* __restrict__ C,
                       int K, int ldc, int wsel)
{
    const float* W = (wsel == 1) ? g_qw_ptr : (wsel == 2) ? g_ow_ptr : Wparam;

    __shared__ float As[16][64];
    __shared__ float Ws[16][64];

    const int tid = threadIdx.x;
    const int tx  = tid & 15;
    const int ty  = tid >> 4;
    const int m0  = blockIdx.y * 64;
    const int n0  = blockIdx.x * 64;
    const int lr  = tid >> 2;
    const int lc  = (tid & 3) * 4;

    const float* Ap = A + (size_t)(m0 + lr) * K + lc;
    const float* Wp = W + (size_t)(n0 + lr) * K + lc;

    float acc[4][4];
#pragma unroll
    for (int i = 0; i < 4; i++)
#pragma unroll
        for (int j = 0; j < 4; j++) acc[i][j] = 0.f;

    for (int k0 = 0; k0 < K; k0 += 16) {
        float4 a = *(const float4*)(Ap + k0);
        float4 w = *(const float4*)(Wp + k0);
        As[lc+0][lr] = a.x; As[lc+1][lr] = a.y; As[lc+2][lr] = a.z; As[lc+3][lr] = a.w;
        Ws[lc+0][lr] = w.x; Ws[lc+1][lr] = w.y; Ws[lc+2][lr] = w.z; Ws[lc+3][lr] = w.w;
        __syncthreads();

#pragma unroll
        for (int kk = 0; kk < 16; kk++) {
            float av[4], wv[4];
            *(float4*)av = *(const float4*)&As[kk][ty*4];
            *(float4*)wv = *(const float4*)&Ws[kk][tx*4];
#pragma unroll
            for (int i = 0; i < 4; i++)
#pragma unroll
                for (int j = 0; j < 4; j++)
                    acc[i][j] += av[i] * wv[j];
        }
        __syncthreads();
    }

#pragma unroll
    for (int i = 0; i < 4; i++) {
        float* cp = C + (size_t)(m0 + ty*4 + i) * ldc + n0;
#pragma unroll
        for (int j = 0; j < 4; j++) {
            float v = acc[i][j];
            if (bias) v += bias[n0 + tx*4 + j];
            cp[tx*4 + j] = v;
        }
    }
}

// ---------------------------------------------------------------------------
// Scatter + RoPE (NeoX pairing, theta=1e4, NEGATED rotation sign this round):
//   out[d]    = x1*c + x2*s
//   out[d+64] = x2*c - x1*s
// mode 0: q (rope). mode 1: k (rope). mode 2: v (copy).
// ---------------------------------------------------------------------------
__global__ void scatter_rope(int mode, int H, int col0, int total)
{
    int idx = blockIdx.x * 256 + threadIdx.x;
    if (idx >= total) return;
    const int d = idx & 63;
    const int h = (idx >> 6) % H;
    const int m = idx / (64 * H);
    const int b = m >> 11;
    const int s = m & (S_LEN - 1);

    const float* src = g_qkv + (size_t)m * NTOT + col0 + h * HD;
    float* dst = (mode == 0) ? g_q : (mode == 1) ? g_k : g_v;
    float* dp = dst + ((size_t)(b * H + h) * S_LEN + s) * HD;

    if (mode < 2) {
        const float x1 = src[d];
        const float x2 = src[d + 64];
        double invf = pow(10000.0, -(double)d / 64.0);
        double cs, sn;
        sincos((double)s * invf, &cs, &sn);
        const float c = (float)cs, sf = (float)sn;
        dp[d]      = x1 * c + x2 * sf;   // NEGATED rotation
        dp[d + 64] = x2 * c - x1 * sf;
    } else {
        dp[d]      = src[d];
        dp[d + 64] = src[d + 64];
    }
}

// ---------------------------------------------------------------------------
// Scores: g_s[bh][q][k] = scale * (Q[q].K[k]) + mask[q][k].
// grid (kt=32, qt=32, bh=32).
// ---------------------------------------------------------------------------
__global__ void score64()
{
    const int kt = blockIdx.x;
    const int qt = blockIdx.y;
    const int bh = blockIdx.z;
    const int b = bh >> 4, h = bh & 15, kvh = h >> 2;

    const float* Q  = g_q + (size_t)(b * NHEADS + h) * S_LEN * HD;
    const float* Kp = g_k + (size_t)(b * NKV + kvh) * S_LEN * HD;
    const float* M  = g_mask_ptr;
    float* Sout = g_s + (size_t)bh * S_LEN * S_LEN;

    const int q0 = qt * 64;
    const int k0t = kt * 64;

    __shared__ float As[16][64];
    __shared__ float Ws[16][64];

    const int tid = threadIdx.x;
    const int tx = tid & 15, ty = tid >> 4;
    const int lr = tid >> 2;
    const int lc = (tid & 3) * 4;

    const float* Ap = Q  + (size_t)(q0  + lr) * HD + lc;
    const float* Wp = Kp + (size_t)(k0t + lr) * HD + lc;

    float acc[4][4];
#pragma unroll
    for (int i = 0; i < 4; i++)
#pragma unroll
        for (int j = 0; j < 4; j++) acc[i][j] = 0.f;

    for (int k0 = 0; k0 < HD; k0 += 16) {
        float4 a = *(const float4*)(Ap + k0);
        float4 w = *(const float4*)(Wp + k0);
        As[lc+0][lr] = a.x; As[lc+1][lr] = a.y; As[lc+2][lr] = a.z; As[lc+3][lr] = a.w;
        Ws[lc+0][lr] = w.x; Ws[lc+1][lr] = w.y; Ws[lc+2][lr] = w.z; Ws[lc+3][lr] = w.w;
        __syncthreads();

#pragma unroll
        for (int kk = 0; kk < 16; kk++) {
            float av[4], wv[4];
            *(float4*)av = *(const float4*)&As[kk][ty*4];
            *(float4*)wv = *(const float4*)&Ws[kk][tx*4];
#pragma unroll
            for (int i = 0; i < 4; i++)
#pragma unroll
                for (int j = 0; j < 4; j++)
                    acc[i][j] += av[i] * wv[j];
        }
        __syncthreads();
    }

    const float scale = 0.08838834764831845f;  // 1/sqrt(128)
#pragma unroll
    for (int i = 0; i < 4; i++) {
        const int q = q0 + ty*4 + i;
#pragma unroll
        for (int j = 0; j < 4; j++) {
            const int k = k0t + tx*4 + j;
            Sout[(size_t)q * S_LEN + k] =
                acc[i][j] * scale + M[(size_t)q * S_LEN + k];
        }
    }
}

// ---------------------------------------------------------------------------
// Softmax: one warp per row q, full row (mask already applied).
// ---------------------------------------------------------------------------
__global__ void softmax_kernel()
{
    const int warp = threadIdx.x >> 5;
    const int lane = threadIdx.x & 31;
    const int row_id = blockIdx.x * 4 + warp;
    const int bh = row_id >> 11;
    const int q  = row_id & (S_LEN - 1);

    float* row = g_s + ((size_t)bh * S_LEN + q) * S_LEN;

    float v[64];
    float m = -3.4e38f;
#pragma unroll
    for (int i = 0; i < 64; i++) {
        v[i] = row[lane + i * 32];
        m = fmaxf(m, v[i]);
    }
#pragma unroll
    for (int o = 16; o > 0; o >>= 1)
        m = fmaxf(m, __shfl_xor_sync(0xffffffffu, m, o));

    float l = 0.f;
#pragma unroll
    for (int i = 0; i < 64; i++) {
        v[i] = __expf(v[i] - m);
        l += v[i];
    }
#pragma unroll
    for (int o = 16; o > 0; o >>= 1)
        l += __shfl_xor_sync(0xffffffffu, l, o);

    const float inv = 1.f / l;
#pragma unroll
    for (int i = 0; i < 64; i++)
        row[lane + i * 32] = v[i] * inv;
}

// ---------------------------------------------------------------------------
// PV: g_attn[b, q, h*HD + d] = sum_k P[bh][q][k] * V[k][d].
// ---------------------------------------------------------------------------
__global__ void pv64()
{
    const int dt = blockIdx.x;
    const int qt = blockIdx.y;
    const int bh = blockIdx.z;
    const int b = bh >> 4, h = bh & 15, kvh = h >> 2;

    const float* P = g_s + (size_t)bh * S_LEN * S_LEN;
    const float* V = g_v + (size_t)(b * NKV + kvh) * S_LEN * HD;

    const int q0 = qt * 64;
    const int d0 = dt * 64;

    __shared__ float As[16][64];
    __shared__ float Vs[16][64];

    const int tid = threadIdx.x;
    const int tx = tid & 15, ty = tid >> 4;
    const int lr = tid >> 2;
    const int lc = (tid & 3) * 4;
    const int vr = tid >> 4;
    const int vc = (tid & 15) * 4;

    float acc[4][4];
#pragma unroll
    for (int i = 0; i < 4; i++)
#pragma unroll
        for (int j = 0; j < 4; j++) acc[i][j] = 0.f;

    for (int k0 = 0; k0 < S_LEN; k0 += 16) {
        float4 a = *(const float4*)(P + (size_t)(q0 + lr) * S_LEN + k0 + lc);
        As[lc+0][lr] = a.x; As[lc+1][lr] = a.y; As[lc+2][lr] = a.z; As[lc+3][lr] = a.w;
        float4 v = *(const float4*)(V + (size_t)(k0 + vr) * HD + d0 + vc);
        *(float4*)&Vs[vr][vc] = v;
        __syncthreads();

#pragma unroll
        for (int kk = 0; kk < 16; kk++) {
            float av[4], vv[4];
            *(float4*)av = *(const float4*)&As[kk][ty*4];
            *(float4*)vv = *(const float4*)&Vs[kk][tx*4];
#pragma unroll
            for (int i = 0; i < 4; i++)
#pragma unroll
                for (int j = 0; j < 4; j++)
                    acc[i][j] += av[i] * vv[j];
        }
        __syncthreads();
    }

#pragma unroll
    for (int i = 0; i < 4; i++) {
        float* op = g_attn + ((size_t)(b * S_LEN + q0 + ty*4 + i)) * HIDDEN + h * HD + d0;
#pragma unroll
        for (int j = 0; j < 4; j++)
            op[tx*4 + j] = acc[i][j];
    }
}

// ---------------------------------------------------------------------------
extern "C" void kernel_launch(void* const* d_in, const int* in_sizes, int n_in,
                              void* d_out, int out_size)
{
    int idx8M = -1, idxQB = -1;
    int idx4M[3] = {1, 2, 8};
    int idx1M[2] = {4, 6};
    int idx512[2] = {5, 7};
    int n4 = 0, n1 = 0, n5 = 0;
    for (int i = 0; i < n_in; i++) {
        switch (in_sizes[i]) {
            case 8388608: idx8M = i; break;
            case 2048:    idxQB = i; break;
            case 4194304: if (n4 < 3) idx4M[n4++] = i; break;
            case 1048576: if (n1 < 2) idx1M[n1++] = i; break;
            case 512:     if (n5 < 2) idx512[n5++] = i; break;
            default: break;
        }
    }
    const float* hs = (const float*)d_in[idx8M];
    const float* qb = (const float*)d_in[idxQB];
    const float* kw = (const float*)d_in[idx1M[0]];
    const float* vw = (const float*)d_in[idx1M[1]];
    const float* kb = (const float*)d_in[idx512[0]];
    const float* vb = (const float*)d_in[idx512[1]];
    const int wFirst = (idx1M[0] < idx512[0]) ? 1 : 0;

    float* out = (float*)d_out;

    float* qkv_flat;
    cudaGetSymbolAddress((void**)&qkv_flat, g_qkv);
    float* attn_flat;
    cudaGetSymbolAddress((void**)&attn_flat, g_attn);

    // 0) Resolve {mask, q_w, o_w} by content + convention (device side)
    resolve_kernel<<<1, 256>>>((const float*)d_in[idx4M[0]],
                               (const float*)d_in[idx4M[1]],
                               (const float*)d_in[idx4M[2]], wFirst);

    // 1) QKV projections into flat buffer [4096, 3072]
    gemm64<<<dim3(NQ/64,   MROWS/64), 256>>>(hs, nullptr, qb, qkv_flat,           HIDDEN, NTOT, 1);
    gemm64<<<dim3(NKVD/64, MROWS/64), 256>>>(hs, kw,      kb, qkv_flat + NQ,      HIDDEN, NTOT, 0);
    gemm64<<<dim3(NKVD/64, MROWS/64), 256>>>(hs, vw,      vb, qkv_flat + NQ+NKVD, HIDDEN, NTOT, 0);

    // 2) Scatter + RoPE (NeoX pairing, theta=1e4, NEGATED rotation sign)
    {
        int tq = MROWS * NHEADS * 64;
        int tk = MROWS * NKV * 64;
        scatter_rope<<<(tq + 255)/256, 256>>>(0, NHEADS, 0,        tq);
        scatter_rope<<<(tk + 255)/256, 256>>>(1, NKV,    NQ,       tk);
        scatter_rope<<<(tk + 255)/256, 256>>>(2, NKV,    NQ+NKVD,  tk);
    }

    // 3) Scores with provided mask (full S x S)
    score64<<<dim3(S_LEN/64, S_LEN/64, BHQ), 256>>>();

    // 4) Row softmax (full row)
    softmax_kernel<<<(BHQ * S_LEN)/4, 128>>>();

    // 5) P @ V (full k range)
    pv64<<<dim3(HD/64, S_LEN/64, BHQ), 256>>>();

    // 6) Output projection
    gemm64<<<dim3(HIDDEN/64, MROWS/64), 256>>>(attn_flat, nullptr, nullptr, out, HIDDEN, HIDDEN, 2);
}

// round 15
// speedup vs baseline: 1.6123x; 1.6123x over previous
#include <cuda_runtime.h>
#include <math.h>
#include <stdint.h>

#define S_LEN  2048
#define HIDDEN 2048
#define NHEADS 16
#define NKV    4
#define HD     128
#define BATCH  2
#define NQ     (NHEADS*HD)          // 2048
#define NKVD   (NKV*HD)             // 512
#define NTOT   (NQ + 2*NKVD)        // 3072
#define MROWS  (BATCH*S_LEN)        // 4096
#define BHQ    (BATCH*NHEADS)       // 32
#define MASK_N 4194304

// Scratch (device globals)
__device__ float g_qkv[(size_t)MROWS*NTOT];
__device__ float g_q[(size_t)BATCH*NHEADS*S_LEN*HD];
__device__ float g_k[(size_t)BATCH*NKV*S_LEN*HD];
__device__ float g_v[(size_t)BATCH*NKV*S_LEN*HD];
__device__ float g_attn[(size_t)BATCH*S_LEN*NHEADS*HD];
__device__ float g_s[(size_t)BHQ*S_LEN*S_LEN];

__device__ const float* g_qw_ptr;
__device__ const float* g_ow_ptr;
__device__ const float* g_mask_ptr;

// ---------------------------------------------------------------------------
// Resolve {mask, q_w, o_w}: subsampled min-scan (mask is ~50% -1e9).
// ---------------------------------------------------------------------------
__global__ void resolve_kernel(const float* c0, const float* c1, const float* c2,
                               int wFirst)
{
    __shared__ float smin[3][256];
    const float* c[3] = {c0, c1, c2};
    const int tid = threadIdx.x;

    for (int i = 0; i < 3; i++) {
        float mn = 3.4e38f;
        for (int e = tid * 1024; e < MASK_N; e += 256 * 1024)
            mn = fminf(mn, c[i][e]);
        smin[i][tid] = mn;
    }
    __syncthreads();
    if (tid == 0) {
        float mn[3];
        for (int i = 0; i < 3; i++) {
            float m = 3.4e38f;
            for (int t = 0; t < 256; t++) m = fminf(m, smin[i][t]);
            mn[i] = m;
        }
        int mi = 0;
        if (mn[1] < mn[mi]) mi = 1;
        if (mn[2] < mn[mi]) mi = 2;
        g_mask_ptr = c[mi];
        const float* nm[2];
        int j = 0;
        for (int i = 0; i < 3; i++)
            if (i != mi) nm[j++] = c[i];
        if (wFirst) { g_qw_ptr = nm[0]; g_ow_ptr = nm[1]; }
        else        { g_qw_ptr = nm[1]; g_ow_ptr = nm[0]; }
    }
}

// ---------------------------------------------------------------------------
// TF32 helpers
// ---------------------------------------------------------------------------
__device__ __forceinline__ void split_tf32(float x, uint32_t& hi, uint32_t& lo)
{
    uint32_t h;
    asm("cvt.rna.tf32.f32 %0, %1;" : "=r"(h) : "f"(x));
    float hf = __uint_as_float(h);
    float lf = x - hf;
    uint32_t l;
    asm("cvt.rna.tf32.f32 %0, %1;" : "=r"(l) : "f"(lf));
    hi = h; lo = l;
}

__device__ __forceinline__ void mma_tf32(float* c, const uint32_t* a, const uint32_t* b)
{
    asm volatile(
        "mma.sync.aligned.m16n8k8.row.col.f32.tf32.tf32.f32 "
        "{%0,%1,%2,%3}, {%4,%5,%6,%7}, {%8,%9}, {%0,%1,%2,%3};"
        : "+f"(c[0]), "+f"(c[1]), "+f"(c[2]), "+f"(c[3])
        : "r"(a[0]), "r"(a[1]), "r"(a[2]), "r"(a[3]), "r"(b[0]), "r"(b[1]));
}

// ---------------------------------------------------------------------------
// 3xTF32 GEMM, block 64(m) x 128(n), BK=16, 256 threads (8 warps, 2x4 grid,
// warp tile 32x32, m16n8k8 frags 2x4 per warp).
// MODE 0: fused QKV proj   (A=hs, B=W[n][k] n-major, C=g_qkv+bias)
// MODE 1: scores           (A=Q, B=K n-major, C=g_s scaled + mask)
// MODE 2: PV               (A=P, B=V[k][n] k-major, C=g_attn)
// MODE 3: O proj           (A=g_attn, B=o_w n-major, C=out)
// ---------------------------------------------------------------------------
template<int MODE>
__global__ __launch_bounds__(256)
void mma_gemm(const float* __restrict__ hs,
              const float* __restrict__ kw, const float* __restrict__ vw,
              const float* __restrict__ qb, const float* __restrict__ kb,
              const float* __restrict__ vb,
              float* __restrict__ Cout)
{
    __shared__ uint32_t AsH[16][68], AsL[16][68];
    __shared__ uint32_t BsH[16][132], BsL[16][132];

    const int tid  = threadIdx.x;
    const int lane = tid & 31;
    const int wid  = tid >> 5;
    const int wm   = wid >> 2;      // 0..1
    const int wn   = wid & 3;       // 0..3
    const int grp  = lane >> 2;     // 0..7
    const int thr  = lane & 3;      // 0..3

    int m0, n0, bh = 0, b = 0, h = 0, kvh = 0, KDIM;
    const float* Aptr;  const float* Bptr;
    const float* bias = nullptr;
    int lda, ldb, nlocal0 = 0;

    if (MODE == 0) {
        m0 = blockIdx.y * 64;  n0 = blockIdx.x * 128;  KDIM = HIDDEN;
        Aptr = hs; lda = HIDDEN; ldb = HIDDEN;
        if (n0 < NQ)            { Bptr = g_qw_ptr + (size_t)n0 * HIDDEN;          bias = qb; nlocal0 = n0; }
        else if (n0 < NQ+NKVD)  { Bptr = kw + (size_t)(n0 - NQ) * HIDDEN;         bias = kb; nlocal0 = n0 - NQ; }
        else                    { Bptr = vw + (size_t)(n0 - NQ - NKVD) * HIDDEN;  bias = vb; nlocal0 = n0 - NQ - NKVD; }
        Aptr += (size_t)m0 * HIDDEN;
    } else if (MODE == 1) {
        m0 = blockIdx.y * 64;  n0 = blockIdx.x * 128;  KDIM = HD;
        bh = blockIdx.z; b = bh >> 4; h = bh & 15; kvh = h >> 2;
        Aptr = g_q + ((size_t)(b * NHEADS + h) * S_LEN + m0) * HD;  lda = HD;
        Bptr = g_k + ((size_t)(b * NKV + kvh) * S_LEN + n0) * HD;   ldb = HD;
    } else if (MODE == 2) {
        m0 = blockIdx.x * 64;  n0 = 0;  KDIM = S_LEN;
        bh = blockIdx.y; b = bh >> 4; h = bh & 15; kvh = h >> 2;
        Aptr = g_s + (size_t)bh * S_LEN * S_LEN + (size_t)m0 * S_LEN;  lda = S_LEN;
        Bptr = g_v + (size_t)(b * NKV + kvh) * S_LEN * HD;             ldb = HD;
    } else {
        m0 = blockIdx.y * 64;  n0 = blockIdx.x * 128;  KDIM = HIDDEN;
        Aptr = g_attn + (size_t)m0 * HIDDEN;  lda = HIDDEN;
        Bptr = g_ow_ptr + (size_t)n0 * HIDDEN;  ldb = HIDDEN;
    }

    float acc[2][4][4];
#pragma unroll
    for (int mi = 0; mi < 2; mi++)
#pragma unroll
        for (int ni = 0; ni < 4; ni++)
#pragma unroll
            for (int e = 0; e < 4; e++) acc[mi][ni][e] = 0.f;

    const int arow = tid >> 2;          // 0..63
    const int akq  = (tid & 3) * 4;

    for (int k0 = 0; k0 < KDIM; k0 += 16) {
        // Stage A tile (64 x 16), split hi/lo
        {
            float4 a = *(const float4*)(Aptr + (size_t)arow * lda + k0 + akq);
            uint32_t h0, l0;
            split_tf32(a.x, h0, l0); AsH[akq+0][arow] = h0; AsL[akq+0][arow] = l0;
            split_tf32(a.y, h0, l0); AsH[akq+1][arow] = h0; AsL[akq+1][arow] = l0;
            split_tf32(a.z, h0, l0); AsH[akq+2][arow] = h0; AsL[akq+2][arow] = l0;
            split_tf32(a.w, h0, l0); AsH[akq+3][arow] = h0; AsL[akq+3][arow] = l0;
        }
        // Stage B tile (16 x 128 in Bs[k][n]), split hi/lo
#pragma unroll
        for (int t = 0; t < 2; t++) {
            int fi = (tid << 1) | t;      // 0..511
            float4 w;
            int kq, nr;
            if (MODE == 2) {
                int kr = fi >> 5;         // 0..15
                int nc = (fi & 31) * 4;   // 0..124
                w = *(const float4*)(Bptr + (size_t)(k0 + kr) * ldb + nc);
                kq = kr; nr = nc;
                uint32_t h0, l0;
                split_tf32(w.x, h0, l0); BsH[kq][nr+0] = h0; BsL[kq][nr+0] = l0;
                split_tf32(w.y, h0, l0); BsH[kq][nr+1] = h0; BsL[kq][nr+1] = l0;
                split_tf32(w.z, h0, l0); BsH[kq][nr+2] = h0; BsL[kq][nr+2] = l0;
                split_tf32(w.w, h0, l0); BsH[kq][nr+3] = h0; BsL[kq][nr+3] = l0;
            } else {
                nr = fi >> 2;             // 0..127
                kq = (fi & 3) * 4;
                w = *(const float4*)(Bptr + (size_t)nr * ldb + k0 + kq);
                uint32_t h0, l0;
                split_tf32(w.x, h0, l0); BsH[kq+0][nr] = h0; BsL[kq+0][nr] = l0;
                split_tf32(w.y, h0, l0); BsH[kq+1][nr] = h0; BsL[kq+1][nr] = l0;
                split_tf32(w.z, h0, l0); BsH[kq+2][nr] = h0; BsL[kq+2][nr] = l0;
                split_tf32(w.w, h0, l0); BsH[kq+3][nr] = h0; BsL[kq+3][nr] = l0;
            }
        }
        __syncthreads();

#pragma unroll
        for (int kk = 0; kk < 16; kk += 8) {
            uint32_t ah[2][4], al[2][4], bhf[4][2], blf[4][2];
#pragma unroll
            for (int mi = 0; mi < 2; mi++) {
                int mb = wm * 32 + mi * 16;
                ah[mi][0] = AsH[kk+thr  ][mb+grp  ];
                ah[mi][1] = AsH[kk+thr  ][mb+grp+8];
                ah[mi][2] = AsH[kk+thr+4][mb+grp  ];
                ah[mi][3] = AsH[kk+thr+4][mb+grp+8];
                al[mi][0] = AsL[kk+thr  ][mb+grp  ];
                al[mi][1] = AsL[kk+thr  ][mb+grp+8];
                al[mi][2] = AsL[kk+thr+4][mb+grp  ];
                al[mi][3] = AsL[kk+thr+4][mb+grp+8];
            }
#pragma unroll
            for (int ni = 0; ni < 4; ni++) {
                int nb = wn * 32 + ni * 8;
                bhf[ni][0] = BsH[kk+thr  ][nb+grp];
                bhf[ni][1] = BsH[kk+thr+4][nb+grp];
                blf[ni][0] = BsL[kk+thr  ][nb+grp];
                blf[ni][1] = BsL[kk+thr+4][nb+grp];
            }
#pragma unroll
            for (int mi = 0; mi < 2; mi++)
#pragma unroll
                for (int ni = 0; ni < 4; ni++) {
                    mma_tf32(acc[mi][ni], ah[mi], bhf[ni]);
                    mma_tf32(acc[mi][ni], ah[mi], blf[ni]);
                    mma_tf32(acc[mi][ni], al[mi], bhf[ni]);
                }
        }
        __syncthreads();
    }

    // Epilogue
    const float scale = 0.08838834764831845f;  // 1/sqrt(128)
#pragma unroll
    for (int mi = 0; mi < 2; mi++) {
        int r0 = m0 + wm * 32 + mi * 16 + grp;
#pragma unroll
        for (int ni = 0; ni < 4; ni++) {
            int cb = wn * 32 + ni * 8 + 2 * thr;   // col within block
#pragma unroll
            for (int e = 0; e < 4; e++) {
                int r = r0 + (e >> 1) * 8;
                int cc = cb + (e & 1);
                float v = acc[mi][ni][e];
                if (MODE == 0) {
                    v += bias[nlocal0 + cc];
                    g_qkv[(size_t)r * NTOT + n0 + cc] = v;
                } else if (MODE == 1) {
                    int kcol = n0 + cc;
                    g_s[(size_t)bh * S_LEN * S_LEN + (size_t)r * S_LEN + kcol] =
                        v * scale + g_mask_ptr[(size_t)r * S_LEN + kcol];
                } else if (MODE == 2) {
                    g_attn[((size_t)(b * S_LEN + r)) * HIDDEN + h * HD + cc] = v;
                } else {
                    Cout[(size_t)r * HIDDEN + n0 + cc] = v;
                }
            }
        }
    }
}

// ---------------------------------------------------------------------------
// Scatter + RoPE (NeoX pairing, theta=1e4, NEGATED rotation — load-bearing!):
//   out[d]    = x1*c + x2*s
//   out[d+64] = x2*c - x1*s
// ---------------------------------------------------------------------------
__global__ void scatter_rope(int mode, int H, int col0, int total)
{
    int idx = blockIdx.x * 256 + threadIdx.x;
    if (idx >= total) return;
    const int d = idx & 63;
    const int h = (idx >> 6) % H;
    const int m = idx / (64 * H);
    const int b = m >> 11;
    const int s = m & (S_LEN - 1);

    const float* src = g_qkv + (size_t)m * NTOT + col0 + h * HD;
    float* dst = (mode == 0) ? g_q : (mode == 1) ? g_k : g_v;
    float* dp = dst + ((size_t)(b * H + h) * S_LEN + s) * HD;

    if (mode < 2) {
        const float x1 = src[d];
        const float x2 = src[d + 64];
        double invf = pow(10000.0, -(double)d / 64.0);
        double cs, sn;
        sincos((double)s * invf, &cs, &sn);
        const float c = (float)cs, sf = (float)sn;
        dp[d]      = x1 * c + x2 * sf;   // NEGATED rotation
        dp[d + 64] = x2 * c - x1 * sf;
    } else {
        dp[d]      = src[d];
        dp[d + 64] = src[d + 64];
    }
}

// ---------------------------------------------------------------------------
// Softmax: one warp per row q, full row (mask already applied in scores).
// ---------------------------------------------------------------------------
__global__ void softmax_kernel()
{
    const int warp = threadIdx.x >> 5;
    const int lane = threadIdx.x & 31;
    const int row_id = blockIdx.x * 4 + warp;
    const int bh = row_id >> 11;
    const int q  = row_id & (S_LEN - 1);

    float* row = g_s + ((size_t)bh * S_LEN + q) * S_LEN;

    float v[64];
    float m = -3.4e38f;
#pragma unroll
    for (int i = 0; i < 64; i++) {
        v[i] = row[lane + i * 32];
        m = fmaxf(m, v[i]);
    }
#pragma unroll
    for (int o = 16; o > 0; o >>= 1)
        m = fmaxf(m, __shfl_xor_sync(0xffffffffu, m, o));

    float l = 0.f;
#pragma unroll
    for (int i = 0; i < 64; i++) {
        v[i] = __expf(v[i] - m);
        l += v[i];
    }
#pragma unroll
    for (int o = 16; o > 0; o >>= 1)
        l += __shfl_xor_sync(0xffffffffu, l, o);

    const float inv = 1.f / l;
#pragma unroll
    for (int i = 0; i < 64; i++)
        row[lane + i * 32] = v[i] * inv;
}

// ---------------------------------------------------------------------------
extern "C" void kernel_launch(void* const* d_in, const int* in_sizes, int n_in,
                              void* d_out, int out_size)
{
    int idx8M = -1, idxQB = -1;
    int idx4M[3] = {1, 2, 8};
    int idx1M[2] = {4, 6};
    int idx512[2] = {5, 7};
    int n4 = 0, n1 = 0, n5 = 0;
    for (int i = 0; i < n_in; i++) {
        switch (in_sizes[i]) {
            case 8388608: idx8M = i; break;
            case 2048:    idxQB = i; break;
            case 4194304: if (n4 < 3) idx4M[n4++] = i; break;
            case 1048576: if (n1 < 2) idx1M[n1++] = i; break;
            case 512:     if (n5 < 2) idx512[n5++] = i; break;
            default: break;
        }
    }
    const float* hs = (const float*)d_in[idx8M];
    const float* qb = (const float*)d_in[idxQB];
    const float* kw = (const float*)d_in[idx1M[0]];
    const float* vw = (const float*)d_in[idx1M[1]];
    const float* kb = (const float*)d_in[idx512[0]];
    const float* vb = (const float*)d_in[idx512[1]];
    const int wFirst = (idx1M[0] < idx512[0]) ? 1 : 0;

    float* out = (float*)d_out;

    // 0) Resolve {mask, q_w, o_w} (subsampled)
    resolve_kernel<<<1, 256>>>((const float*)d_in[idx4M[0]],
                               (const float*)d_in[idx4M[1]],
                               (const float*)d_in[idx4M[2]], wFirst);

    // 1) Fused QKV projection (3xTF32 mma)
    mma_gemm<0><<<dim3(NTOT/128, MROWS/64), 256>>>(hs, kw, vw, qb, kb, vb, nullptr);

    // 2) Scatter + RoPE (NEGATED sign)
    {
        int tq = MROWS * NHEADS * 64;
        int tk = MROWS * NKV * 64;
        scatter_rope<<<(tq + 255)/256, 256>>>(0, NHEADS, 0,        tq);
        scatter_rope<<<(tk + 255)/256, 256>>>(1, NKV,    NQ,       tk);
        scatter_rope<<<(tk + 255)/256, 256>>>(2, NKV,    NQ+NKVD,  tk);
    }

    // 3) Scores + mask (3xTF32 mma)
    mma_gemm<1><<<dim3(S_LEN/128, S_LEN/64, BHQ), 256>>>(nullptr, nullptr, nullptr,
                                                         nullptr, nullptr, nullptr, nullptr);

    // 4) Row softmax
    softmax_kernel<<<(BHQ * S_LEN)/4, 128>>>();

    // 5) P @ V (3xTF32 mma)
    mma_gemm<2><<<dim3(S_LEN/64, BHQ), 256>>>(nullptr, nullptr, nullptr,
                                              nullptr, nullptr, nullptr, nullptr);

    // 6) Output projection (3xTF32 mma)
    mma_gemm<3><<<dim3(HIDDEN/128, MROWS/64), 256>>>(nullptr, nullptr, nullptr,
                                                     nullptr, nullptr, nullptr, out);
}

// round 16
// speedup vs baseline: 2.4506x; 1.5199x over previous
#include <cuda_runtime.h>
#include <math.h>
#include <stdint.h>

#define S_LEN  2048
#define HIDDEN 2048
#define NHEADS 16
#define NKV    4
#define HD     128
#define BATCH  2
#define NQ     (NHEADS*HD)          // 2048
#define NKVD   (NKV*HD)             // 512
#define NTOT   (NQ + 2*NKVD)        // 3072
#define MROWS  (BATCH*S_LEN)        // 4096
#define BHQ    (BATCH*NHEADS)       // 32
#define MASK_N 4194304

// Scratch (device globals)
__device__ float g_qkv[(size_t)MROWS*NTOT];
__device__ float g_q[(size_t)BATCH*NHEADS*S_LEN*HD];
__device__ float g_k[(size_t)BATCH*NKV*S_LEN*HD];
__device__ float g_attn[(size_t)BATCH*S_LEN*NHEADS*HD];
__device__ float g_s[(size_t)BHQ*S_LEN*S_LEN];
__device__ float g_rc[S_LEN*64];   // rope cos table
__device__ float g_rs[S_LEN*64];   // rope sin table

__device__ const float* g_qw_ptr;
__device__ const float* g_ow_ptr;
__device__ const float* g_mask_ptr;

// ---------------------------------------------------------------------------
// Resolve {mask, q_w, o_w}: subsampled min-scan (mask is ~50% -1e9).
// ---------------------------------------------------------------------------
__global__ void resolve_kernel(const float* c0, const float* c1, const float* c2,
                               int wFirst)
{
    __shared__ float smin[3][256];
    const float* c[3] = {c0, c1, c2};
    const int tid = threadIdx.x;

    for (int i = 0; i < 3; i++) {
        float mn = 3.4e38f;
        for (int e = tid * 1024; e < MASK_N; e += 256 * 1024)
            mn = fminf(mn, c[i][e]);
        smin[i][tid] = mn;
    }
    __syncthreads();
    if (tid == 0) {
        float mn[3];
        for (int i = 0; i < 3; i++) {
            float m = 3.4e38f;
            for (int t = 0; t < 256; t++) m = fminf(m, smin[i][t]);
            mn[i] = m;
        }
        int mi = 0;
        if (mn[1] < mn[mi]) mi = 1;
        if (mn[2] < mn[mi]) mi = 2;
        g_mask_ptr = c[mi];
        const float* nm[2];
        int j = 0;
        for (int i = 0; i < 3; i++)
            if (i != mi) nm[j++] = c[i];
        if (wFirst) { g_qw_ptr = nm[0]; g_ow_ptr = nm[1]; }
        else        { g_qw_ptr = nm[1]; g_ow_ptr = nm[0]; }
    }
}

// ---------------------------------------------------------------------------
// RoPE table: cos/sin(s * 10000^{-d/64}) computed once in double.
// ---------------------------------------------------------------------------
__global__ void rope_table_kernel()
{
    int idx = blockIdx.x * 256 + threadIdx.x;
    if (idx >= S_LEN * 64) return;
    const int d = idx & 63;
    const int s = idx >> 6;
    double invf = pow(10000.0, -(double)d / 64.0);
    double cs, sn;
    sincos((double)s * invf, &cs, &sn);
    g_rc[idx] = (float)cs;
    g_rs[idx] = (float)sn;
}

// ---------------------------------------------------------------------------
// TF32 helpers
// ---------------------------------------------------------------------------
__device__ __forceinline__ void split_tf32(float x, uint32_t& hi, uint32_t& lo)
{
    uint32_t h;
    asm("cvt.rna.tf32.f32 %0, %1;" : "=r"(h) : "f"(x));
    float hf = __uint_as_float(h);
    float lf = x - hf;
    uint32_t l;
    asm("cvt.rna.tf32.f32 %0, %1;" : "=r"(l) : "f"(lf));
    hi = h; lo = l;
}

__device__ __forceinline__ void mma_tf32(float* c, const uint32_t* a, const uint32_t* b)
{
    asm volatile(
        "mma.sync.aligned.m16n8k8.row.col.f32.tf32.tf32.f32 "
        "{%0,%1,%2,%3}, {%4,%5,%6,%7}, {%8,%9}, {%0,%1,%2,%3};"
        : "+f"(c[0]), "+f"(c[1]), "+f"(c[2]), "+f"(c[3])
        : "r"(a[0]), "r"(a[1]), "r"(a[2]), "r"(a[3]), "r"(b[0]), "r"(b[1]));
}

// ---------------------------------------------------------------------------
// 3xTF32 GEMM, block 64(m) x 128(n), BK=16, 256 threads.
// MODE 0: fused QKV proj   (A=hs, B=W[n][k], C=g_qkv+bias)
// MODE 1: scores           (A=Q, B=K, C=g_s scaled+mask; causal tile skip)
// MODE 2: PV               (A=P, B=V from g_qkv k-major, causal k-bound)
// MODE 3: O proj           (A=g_attn, B=o_w, C=out)
// ---------------------------------------------------------------------------
template<int MODE>
__global__ __launch_bounds__(256)
void mma_gemm(const float* __restrict__ hs,
              const float* __restrict__ kw, const float* __restrict__ vw,
              const float* __restrict__ qb, const float* __restrict__ kb,
              const float* __restrict__ vb,
              float* __restrict__ Cout)
{
    __shared__ uint32_t AsH[16][68], AsL[16][68];
    __shared__ uint32_t BsH[16][132], BsL[16][132];

    const int tid  = threadIdx.x;
    const int lane = tid & 31;
    const int wid  = tid >> 5;
    const int wm   = wid >> 2;      // 0..1
    const int wn   = wid & 3;       // 0..3
    const int grp  = lane >> 2;     // 0..7
    const int thr  = lane & 3;      // 0..3

    int m0, n0, bh = 0, b = 0, h = 0, kvh = 0, KDIM;
    const float* Aptr;  const float* Bptr;
    const float* bias = nullptr;
    int lda, ldb, nlocal0 = 0;

    if (MODE == 0) {
        m0 = blockIdx.y * 64;  n0 = blockIdx.x * 128;  KDIM = HIDDEN;
        Aptr = hs; lda = HIDDEN; ldb = HIDDEN;
        if (n0 < NQ)            { Bptr = g_qw_ptr + (size_t)n0 * HIDDEN;          bias = qb; nlocal0 = n0; }
        else if (n0 < NQ+NKVD)  { Bptr = kw + (size_t)(n0 - NQ) * HIDDEN;         bias = kb; nlocal0 = n0 - NQ; }
        else                    { Bptr = vw + (size_t)(n0 - NQ - NKVD) * HIDDEN;  bias = vb; nlocal0 = n0 - NQ - NKVD; }
        Aptr += (size_t)m0 * HIDDEN;
    } else if (MODE == 1) {
        m0 = blockIdx.y * 64;  n0 = blockIdx.x * 128;  KDIM = HD;
        if (n0 > m0 + 63) return;          // causal: whole tile masked
        bh = blockIdx.z; b = bh >> 4; h = bh & 15; kvh = h >> 2;
        Aptr = g_q + ((size_t)(b * NHEADS + h) * S_LEN + m0) * HD;  lda = HD;
        Bptr = g_k + ((size_t)(b * NKV + kvh) * S_LEN + n0) * HD;   ldb = HD;
    } else if (MODE == 2) {
        m0 = blockIdx.x * 64;  n0 = 0;
        KDIM = ((m0 >> 7) + 1) * 128;      // causal prefix (uniform in block)
        bh = blockIdx.y; b = bh >> 4; h = bh & 15; kvh = h >> 2;
        Aptr = g_s + (size_t)bh * S_LEN * S_LEN + (size_t)m0 * S_LEN;  lda = S_LEN;
        Bptr = g_qkv + (size_t)b * S_LEN * NTOT + NQ + NKVD + kvh * HD; ldb = NTOT;
    } else {
        m0 = blockIdx.y * 64;  n0 = blockIdx.x * 128;  KDIM = HIDDEN;
        Aptr = g_attn + (size_t)m0 * HIDDEN;  lda = HIDDEN;
        Bptr = g_ow_ptr + (size_t)n0 * HIDDEN;  ldb = HIDDEN;
    }

    float acc[2][4][4];
#pragma unroll
    for (int mi = 0; mi < 2; mi++)
#pragma unroll
        for (int ni = 0; ni < 4; ni++)
#pragma unroll
            for (int e = 0; e < 4; e++) acc[mi][ni][e] = 0.f;

    const int arow = tid >> 2;          // 0..63
    const int akq  = (tid & 3) * 4;

    for (int k0 = 0; k0 < KDIM; k0 += 16) {
        {
            float4 a = *(const float4*)(Aptr + (size_t)arow * lda + k0 + akq);
            uint32_t h0, l0;
            split_tf32(a.x, h0, l0); AsH[akq+0][arow] = h0; AsL[akq+0][arow] = l0;
            split_tf32(a.y, h0, l0); AsH[akq+1][arow] = h0; AsL[akq+1][arow] = l0;
            split_tf32(a.z, h0, l0); AsH[akq+2][arow] = h0; AsL[akq+2][arow] = l0;
            split_tf32(a.w, h0, l0); AsH[akq+3][arow] = h0; AsL[akq+3][arow] = l0;
        }
#pragma unroll
        for (int t = 0; t < 2; t++) {
            int fi = (tid << 1) | t;      // 0..511
            if (MODE == 2) {
                int kr = fi >> 5;         // 0..15
                int nc = (fi & 31) * 4;   // 0..124
                float4 w = *(const float4*)(Bptr + (size_t)(k0 + kr) * ldb + nc);
                uint32_t h0, l0;
                split_tf32(w.x, h0, l0); BsH[kr][nc+0] = h0; BsL[kr][nc+0] = l0;
                split_tf32(w.y, h0, l0); BsH[kr][nc+1] = h0; BsL[kr][nc+1] = l0;
                split_tf32(w.z, h0, l0); BsH[kr][nc+2] = h0; BsL[kr][nc+2] = l0;
                split_tf32(w.w, h0, l0); BsH[kr][nc+3] = h0; BsL[kr][nc+3] = l0;
            } else {
                int nr = fi >> 2;         // 0..127
                int kq = (fi & 3) * 4;
                float4 w = *(const float4*)(Bptr + (size_t)nr * ldb + k0 + kq);
                uint32_t h0, l0;
                split_tf32(w.x, h0, l0); BsH[kq+0][nr] = h0; BsL[kq+0][nr] = l0;
                split_tf32(w.y, h0, l0); BsH[kq+1][nr] = h0; BsL[kq+1][nr] = l0;
                split_tf32(w.z, h0, l0); BsH[kq+2][nr] = h0; BsL[kq+2][nr] = l0;
                split_tf32(w.w, h0, l0); BsH[kq+3][nr] = h0; BsL[kq+3][nr] = l0;
            }
        }
        __syncthreads();

#pragma unroll
        for (int kk = 0; kk < 16; kk += 8) {
            uint32_t ah[2][4], al[2][4], bhf[4][2], blf[4][2];
#pragma unroll
            for (int mi = 0; mi < 2; mi++) {
                int mb = wm * 32 + mi * 16;
                ah[mi][0] = AsH[kk+thr  ][mb+grp  ];
                ah[mi][1] = AsH[kk+thr  ][mb+grp+8];
                ah[mi][2] = AsH[kk+thr+4][mb+grp  ];
                ah[mi][3] = AsH[kk+thr+4][mb+grp+8];
                al[mi][0] = AsL[kk+thr  ][mb+grp  ];
                al[mi][1] = AsL[kk+thr  ][mb+grp+8];
                al[mi][2] = AsL[kk+thr+4][mb+grp  ];
                al[mi][3] = AsL[kk+thr+4][mb+grp+8];
            }
#pragma unroll
            for (int ni = 0; ni < 4; ni++) {
                int nb = wn * 32 + ni * 8;
                bhf[ni][0] = BsH[kk+thr  ][nb+grp];
                bhf[ni][1] = BsH[kk+thr+4][nb+grp];
                blf[ni][0] = BsL[kk+thr  ][nb+grp];
                blf[ni][1] = BsL[kk+thr+4][nb+grp];
            }
#pragma unroll
            for (int mi = 0; mi < 2; mi++)
#pragma unroll
                for (int ni = 0; ni < 4; ni++) {
                    mma_tf32(acc[mi][ni], ah[mi], bhf[ni]);
                    mma_tf32(acc[mi][ni], ah[mi], blf[ni]);
                    mma_tf32(acc[mi][ni], al[mi], bhf[ni]);
                }
        }
        __syncthreads();
    }

    const float scale = 0.08838834764831845f;  // 1/sqrt(128)
#pragma unroll
    for (int mi = 0; mi < 2; mi++) {
        int r0 = m0 + wm * 32 + mi * 16 + grp;
#pragma unroll
        for (int ni = 0; ni < 4; ni++) {
            int cb = wn * 32 + ni * 8 + 2 * thr;
#pragma unroll
            for (int e = 0; e < 4; e++) {
                int r = r0 + (e >> 1) * 8;
                int cc = cb + (e & 1);
                float v = acc[mi][ni][e];
                if (MODE == 0) {
                    v += bias[nlocal0 + cc];
                    g_qkv[(size_t)r * NTOT + n0 + cc] = v;
                } else if (MODE == 1) {
                    int kcol = n0 + cc;
                    g_s[(size_t)bh * S_LEN * S_LEN + (size_t)r * S_LEN + kcol] =
                        v * scale + g_mask_ptr[(size_t)r * S_LEN + kcol];
                } else if (MODE == 2) {
                    g_attn[((size_t)(b * S_LEN + r)) * HIDDEN + h * HD + cc] = v;
                } else {
                    Cout[(size_t)r * HIDDEN + n0 + cc] = v;
                }
            }
        }
    }
}

// ---------------------------------------------------------------------------
// Scatter + RoPE via table (NeoX pairing, NEGATED rotation — load-bearing!):
//   out[d]    = x1*c + x2*s
//   out[d+64] = x2*c - x1*s
// mode 0: q (H=16). mode 1: k (H=4). (V stays in g_qkv; PV reads it there.)
// ---------------------------------------------------------------------------
__global__ void scatter_rope(int mode, int H, int col0, int total)
{
    int idx = blockIdx.x * 256 + threadIdx.x;
    if (idx >= total) return;
    const int d = idx & 63;
    const int h = (idx >> 6) % H;
    const int m = idx / (64 * H);
    const int b = m >> 11;
    const int s = m & (S_LEN - 1);

    const float* src = g_qkv + (size_t)m * NTOT + col0 + h * HD;
    float* dst = (mode == 0) ? g_q : g_k;
    float* dp = dst + ((size_t)(b * H + h) * S_LEN + s) * HD;

    const float x1 = src[d];
    const float x2 = src[d + 64];
    const float c  = g_rc[(s << 6) + d];
    const float sf = g_rs[(s << 6) + d];
    dp[d]      = x1 * c + x2 * sf;   // NEGATED rotation
    dp[d + 64] = x2 * c - x1 * sf;
}

// ---------------------------------------------------------------------------
// Softmax: one warp per row q, causal prefix kmax = ((q>>7)+1)*128.
// ---------------------------------------------------------------------------
__global__ void softmax_kernel()
{
    const int warp = threadIdx.x >> 5;
    const int lane = threadIdx.x & 31;
    const int row_id = blockIdx.x * 4 + warp;
    const int bh = row_id >> 11;
    const int q  = row_id & (S_LEN - 1);
    const int kmax = ((q >> 7) + 1) * 128;

    float* row = g_s + ((size_t)bh * S_LEN + q) * S_LEN;

    float v[64];
    float m = -3.4e38f;
#pragma unroll
    for (int i = 0; i < 64; i++) {
        const int k = lane + i * 32;
        v[i] = (k < kmax) ? row[k] : -3.4e38f;
        m = fmaxf(m, v[i]);
    }
#pragma unroll
    for (int o = 16; o > 0; o >>= 1)
        m = fmaxf(m, __shfl_xor_sync(0xffffffffu, m, o));

    float l = 0.f;
#pragma unroll
    for (int i = 0; i < 64; i++) {
        v[i] = __expf(v[i] - m);
        l += v[i];
    }
#pragma unroll
    for (int o = 16; o > 0; o >>= 1)
        l += __shfl_xor_sync(0xffffffffu, l, o);

    const float inv = 1.f / l;
#pragma unroll
    for (int i = 0; i < 64; i++) {
        const int k = lane + i * 32;
        if (k < kmax) row[k] = v[i] * inv;
    }
}

// ---------------------------------------------------------------------------
extern "C" void kernel_launch(void* const* d_in, const int* in_sizes, int n_in,
                              void* d_out, int out_size)
{
    int idx8M = -1, idxQB = -1;
    int idx4M[3] = {1, 2, 8};
    int idx1M[2] = {4, 6};
    int idx512[2] = {5, 7};
    int n4 = 0, n1 = 0, n5 = 0;
    for (int i = 0; i < n_in; i++) {
        switch (in_sizes[i]) {
            case 8388608: idx8M = i; break;
            case 2048:    idxQB = i; break;
            case 4194304: if (n4 < 3) idx4M[n4++] = i; break;
            case 1048576: if (n1 < 2) idx1M[n1++] = i; break;
            case 512:     if (n5 < 2) idx512[n5++] = i; break;
            default: break;
        }
    }
    const float* hs = (const float*)d_in[idx8M];
    const float* qb = (const float*)d_in[idxQB];
    const float* kw = (const float*)d_in[idx1M[0]];
    const float* vw = (const float*)d_in[idx1M[1]];
    const float* kb = (const float*)d_in[idx512[0]];
    const float* vb = (const float*)d_in[idx512[1]];
    const int wFirst = (idx1M[0] < idx512[0]) ? 1 : 0;

    float* out = (float*)d_out;

    // 0) Resolve {mask, q_w, o_w} + rope tables (cheap, overlapped)
    resolve_kernel<<<1, 256>>>((const float*)d_in[idx4M[0]],
                               (const float*)d_in[idx4M[1]],
                               (const float*)d_in[idx4M[2]], wFirst);
    rope_table_kernel<<<(S_LEN*64 + 255)/256, 256>>>();

    // 1) Fused QKV projection (3xTF32 mma)
    mma_gemm<0><<<dim3(NTOT/128, MROWS/64), 256>>>(hs, kw, vw, qb, kb, vb, nullptr);

    // 2) Scatter + RoPE (NEGATED sign, table-based); V stays in g_qkv
    {
        int tq = MROWS * NHEADS * 64;
        int tk = MROWS * NKV * 64;
        scatter_rope<<<(tq + 255)/256, 256>>>(0, NHEADS, 0,  tq);
        scatter_rope<<<(tk + 255)/256, 256>>>(1, NKV,    NQ, tk);
    }

    // 3) Scores + mask (3xTF32 mma, causal tile skip)
    mma_gemm<1><<<dim3(S_LEN/128, S_LEN/64, BHQ), 256>>>(nullptr, nullptr, nullptr,
                                                         nullptr, nullptr, nullptr, nullptr);

    // 4) Row softmax (causal prefix)
    softmax_kernel<<<(BHQ * S_LEN)/4, 128>>>();

    // 5) P @ V (3xTF32 mma, causal k-bound, V from g_qkv)
    mma_gemm<2><<<dim3(S_LEN/64, BHQ), 256>>>(nullptr, nullptr, nullptr,
                                              nullptr, nullptr, nullptr, nullptr);

    // 6) Output projection (3xTF32 mma)
    mma_gemm<3><<<dim3(HIDDEN/128, MROWS/64), 256>>>(nullptr, nullptr, nullptr,
                                                     nullptr, nullptr, nullptr, out);
}